// round 2
// baseline (speedup 1.0000x reference)
#include <cuda_runtime.h>
#include <math.h>
#include <stdint.h>

// ---------------- scratch (device globals; no allocation allowed) ----------
__device__ float g_xg  [16u*2048u*512u];   // precomputed input gates [B,S,4H]
__device__ float g_lstm[16u*2048u*128u];   // lstm hidden states [B,S,H]
__device__ float g_ctx [16u*2048u*128u];   // attention context [B,S,H]
__device__ float g_ha  [32768u*132u];      // MLP ping buffer (stride 132, padded)
__device__ float g_hb  [32768u*132u];      // MLP pong buffer

__device__ __forceinline__ float sigf(float x) {
    return __fdividef(1.f, 1.f + __expf(-x));
}
__device__ __forceinline__ float tanh_fast(float x) {
    // tanh(x) = 2*sigmoid(2x) - 1
    return fmaf(2.f, sigf(2.f * x), -1.f);
}

// ---------------- K1: xg = x @ W_ih^T + b_ih  ([32768,129]@[129,512]) ------
__global__ void k_xg(const float* __restrict__ x,
                     const float* __restrict__ Wih,
                     const float* __restrict__ bih) {
    extern __shared__ float sm[];
    float* xs = sm;            // [64][132]
    float* ws = sm + 64 * 132; // [64][132]
    const int m0 = blockIdx.x * 64;
    const int g0 = blockIdx.y * 64;
    const int tid = threadIdx.x;

    for (int i = tid; i < 64 * 132; i += 256) {
        int r = i / 132, c = i - r * 132;
        xs[i] = (c < 129) ? x[(size_t)(m0 + r) * 129 + c] : 0.f;
    }
    for (int i = tid; i < 64 * 132; i += 256) {
        int r = i / 132, c = i - r * 132;
        ws[i] = (c < 129) ? Wih[(size_t)(g0 + r) * 129 + c] : 0.f;
    }
    __syncthreads();

    const int ty = tid >> 4, tx = tid & 15;
    float acc[4][4] = {};
    const float4* xs4 = (const float4*)xs;
    const float4* ws4 = (const float4*)ws;

#pragma unroll 3
    for (int k = 0; k < 33; k++) {
        float4 xv[4], wv[4];
#pragma unroll
        for (int i = 0; i < 4; i++) xv[i] = xs4[(4 * ty + i) * 33 + k];
#pragma unroll
        for (int j = 0; j < 4; j++) wv[j] = ws4[(4 * tx + j) * 33 + k];
#pragma unroll
        for (int i = 0; i < 4; i++)
#pragma unroll
            for (int j = 0; j < 4; j++) {
                acc[i][j] += xv[i].x * wv[j].x + xv[i].y * wv[j].y
                           + xv[i].z * wv[j].z + xv[i].w * wv[j].w;
            }
    }

#pragma unroll
    for (int i = 0; i < 4; i++)
#pragma unroll
        for (int j = 0; j < 4; j++) {
            int g = g0 + 4 * tx + j;
            g_xg[(size_t)(m0 + 4 * ty + i) * 512 + g] = acc[i][j] + bih[g];
        }
}

// ---------------- K2: LSTM recurrence (16 blocks, 256 threads) -------------
// thread t: j = t>>1; even -> gates (i: j, g: 256+j); odd -> (f: 128+j, o: 384+j)
// 80 weights/gate in registers, 48/gate streamed from smem, h double-buffered.
__global__ void __launch_bounds__(256, 1)
k_lstm(const float* __restrict__ Whh, const float* __restrict__ bhh) {
    extern __shared__ float sm[];
    float4* wsh = (float4*)sm;            // 24 slots * 256 threads of float4
    float*  hb  = sm + 4 * 24 * 256;      // [2][128] double-buffered h

    const int b = blockIdx.x;
    const int t = threadIdx.x;
    const int j = t >> 1;
    const bool odd = (t & 1);
    const int gA = odd ? (128 + j) : j;
    const int gB = gA + 256;

    const float4* WA = (const float4*)(Whh + (size_t)gA * 128);
    const float4* WB = (const float4*)(Whh + (size_t)gB * 128);
    float4 wA[20], wB[20];
#pragma unroll
    for (int k = 0; k < 20; k++) { wA[k] = WA[k]; wB[k] = WB[k]; }
#pragma unroll
    for (int k = 0; k < 12; k++) {
        wsh[k * 256 + t]        = WA[20 + k];
        wsh[(12 + k) * 256 + t] = WB[20 + k];
    }
    const float bA = bhh[gA], bB = bhh[gB];

    if (t < 128) hb[t] = 0.f;   // initial h = 0 (buffer 0)
    float c = 0.f;

    const float* xgp = g_xg + (size_t)b * 2048 * 512;
    float xgA = xgp[gA], xgB = xgp[gB];
    __syncthreads();

    for (int s = 0; s < 2048; s++) {
        // prefetch next step's input-gate contributions (hides DRAM latency)
        float nA = 0.f, nB = 0.f;
        if (s + 1 < 2048) {
            nA = xgp[(size_t)(s + 1) * 512 + gA];
            nB = xgp[(size_t)(s + 1) * 512 + gB];
        }

        const float4* h4 = (const float4*)(hb + (s & 1) * 128);
        float a = 0.f, d = 0.f;
#pragma unroll
        for (int k = 0; k < 20; k++) {
            float4 hv = h4[k];
            a += wA[k].x * hv.x + wA[k].y * hv.y + wA[k].z * hv.z + wA[k].w * hv.w;
            d += wB[k].x * hv.x + wB[k].y * hv.y + wB[k].z * hv.z + wB[k].w * hv.w;
        }
#pragma unroll
        for (int k = 0; k < 12; k++) {
            float4 hv = h4[20 + k];
            float4 wa = wsh[k * 256 + t];
            float4 wb = wsh[(12 + k) * 256 + t];
            a += wa.x * hv.x + wa.y * hv.y + wa.z * hv.z + wa.w * hv.w;
            d += wb.x * hv.x + wb.y * hv.y + wb.z * hv.z + wb.w * hv.w;
        }

        float pre0 = a + xgA + bA;
        float pre1 = d + xgB + bB;
        float q0 = __shfl_xor_sync(0xffffffffu, pre0, 1);
        float q1 = __shfl_xor_sync(0xffffffffu, pre1, 1);
        float ip, fp, gp, op;
        if (!odd) { ip = pre0; gp = pre1; fp = q0;   op = q1;   }
        else      { ip = q0;   gp = q1;   fp = pre0; op = pre1; }

        c = sigf(fp) * c + sigf(ip) * tanh_fast(gp);
        float h = sigf(op) * tanh_fast(c);

        float* hn = hb + ((s + 1) & 1) * 128;
        if (!odd) {
            hn[j] = h;
            g_lstm[((size_t)b * 2048 + s) * 128 + j] = h;
        }
        xgA = nA; xgB = nB;
        __syncthreads();
    }
}

// ---------------- K3: flash attention (q=k=v=lstm_out), fp32 ---------------
__global__ void k_attn() {
    extern __shared__ float sm[];
    float* qs = sm;                 // [64][132] (only 128 cols used)
    float* ks = sm + 64 * 132;      // [64][132]
    float* ps = ks + 64 * 132;      // [64][68]

    const int b  = blockIdx.y;
    const int r0 = blockIdx.x * 64;
    const float* qsrc = g_lstm + (size_t)b * 2048 * 128;
    const int tid = threadIdx.x;
    const int ty = tid >> 4, tx = tid & 15;
    const float rs = 0.08804509063256238f; // 1/sqrt(129)

    {   // load q tile
        const float4* qg = (const float4*)(qsrc + (size_t)r0 * 128);
        float4* qs4 = (float4*)qs;
        for (int i = tid; i < 2048; i += 256) {
            int row = i >> 5, c = i & 31;
            qs4[row * 33 + c] = qg[row * 32 + c];
        }
    }

    float m[4], l[4], o[4][8];
#pragma unroll
    for (int i = 0; i < 4; i++) {
        m[i] = -1e30f; l[i] = 0.f;
#pragma unroll
        for (int jj = 0; jj < 8; jj++) o[i][jj] = 0.f;
    }

    for (int kt = 0; kt < 32; kt++) {
        __syncthreads();  // previous phase2 done reading ks/ps (also covers q load)
        {
            const float4* kg = (const float4*)(qsrc + (size_t)kt * 64 * 128);
            float4* ks4 = (float4*)ks;
            for (int i = tid; i < 2048; i += 256) {
                int row = i >> 5, c = i & 31;
                ks4[row * 33 + c] = kg[row * 32 + c];
            }
        }
        __syncthreads();

        // phase 1: s = q k^T (4x4 per thread)
        float s[4][4] = {};
        const float4* qs4 = (const float4*)qs;
        const float4* ks4 = (const float4*)ks;
#pragma unroll 4
        for (int k = 0; k < 32; k++) {
            float4 qv[4], kv[4];
#pragma unroll
            for (int i = 0; i < 4; i++) qv[i] = qs4[(4 * ty + i) * 33 + k];
#pragma unroll
            for (int jj = 0; jj < 4; jj++) kv[jj] = ks4[(4 * tx + jj) * 33 + k];
#pragma unroll
            for (int i = 0; i < 4; i++)
#pragma unroll
                for (int jj = 0; jj < 4; jj++) {
                    s[i][jj] += qv[i].x * kv[jj].x + qv[i].y * kv[jj].y
                              + qv[i].z * kv[jj].z + qv[i].w * kv[jj].w;
                }
        }

        float alpha[4];
#pragma unroll
        for (int i = 0; i < 4; i++) {
#pragma unroll
            for (int jj = 0; jj < 4; jj++) s[i][jj] *= rs;
            float vm = fmaxf(fmaxf(s[i][0], s[i][1]), fmaxf(s[i][2], s[i][3]));
#pragma unroll
            for (int dd = 1; dd < 16; dd <<= 1)
                vm = fmaxf(vm, __shfl_xor_sync(0xffffffffu, vm, dd));
            float nm = fmaxf(m[i], vm);
            float sum = 0.f;
#pragma unroll
            for (int jj = 0; jj < 4; jj++) {
                float p = __expf(s[i][jj] - nm);
                s[i][jj] = p; sum += p;
            }
#pragma unroll
            for (int dd = 1; dd < 16; dd <<= 1)
                sum += __shfl_xor_sync(0xffffffffu, sum, dd);
            alpha[i] = __expf(m[i] - nm);
            l[i] = l[i] * alpha[i] + sum;
            m[i] = nm;
        }

#pragma unroll
        for (int i = 0; i < 4; i++)
#pragma unroll
            for (int jj = 0; jj < 4; jj++)
                ps[(4 * ty + i) * 68 + 4 * tx + jj] = s[i][jj];
        __syncthreads();

        // phase 2: o = o*alpha + p @ k   (rows 4ty+i, cols 8tx..8tx+7)
#pragma unroll
        for (int i = 0; i < 4; i++)
#pragma unroll
            for (int jj = 0; jj < 8; jj++) o[i][jj] *= alpha[i];

#pragma unroll 2
        for (int k = 0; k < 64; k++) {
            float4 ka = ks4[k * 33 + 2 * tx];
            float4 kb = ks4[k * 33 + 2 * tx + 1];
#pragma unroll
            for (int i = 0; i < 4; i++) {
                float pv = ps[(4 * ty + i) * 68 + k];
                o[i][0] += pv * ka.x; o[i][1] += pv * ka.y;
                o[i][2] += pv * ka.z; o[i][3] += pv * ka.w;
                o[i][4] += pv * kb.x; o[i][5] += pv * kb.y;
                o[i][6] += pv * kb.z; o[i][7] += pv * kb.w;
            }
        }
    }

    // epilogue
#pragma unroll
    for (int i = 0; i < 4; i++) {
        float inv = 1.f / l[i];
        int row = r0 + 4 * ty + i;
        float4* dst = (float4*)(g_ctx + ((size_t)b * 2048 + row) * 128 + 8 * tx);
        float4 o1 = make_float4(o[i][0] * inv, o[i][1] * inv, o[i][2] * inv, o[i][3] * inv);
        float4 o2 = make_float4(o[i][4] * inv, o[i][5] * inv, o[i][6] * inv, o[i][7] * inv);
        dst[0] = o1; dst[1] = o2;
    }
}

// ---------------- K4: concat(context, RBF kernel feature), pad to 132 ------
__global__ void k_feat(const float* __restrict__ x, const float* __restrict__ pr) {
    const int tid = threadIdx.x;
    const int warp = tid >> 5, lane = tid & 31;
    const size_t mrow = (size_t)blockIdx.x * 8 + warp;

    const float4* c4 = (const float4*)(g_ctx + mrow * 128);
    float4* o4 = (float4*)(g_ha + mrow * 132);
    o4[lane] = c4[lane];

    const float* xr = x  + mrow * 129;
    const float* pp = pr + mrow * 129;
    float ss = 0.f;
    for (int j2 = lane; j2 < 129; j2 += 32) {
        float d = xr[j2] - pp[j2];
        ss += d * d;
    }
#pragma unroll
    for (int dd = 16; dd; dd >>= 1) ss += __shfl_xor_sync(0xffffffffu, ss, dd);
    if (lane == 0)      g_ha[mrow * 132 + 128] = __expf(-ss);
    else if (lane < 4)  g_ha[mrow * 132 + 128 + lane] = 0.f;
}

// ---------------- K5: one MLP layer h = relu(h @ Wc[l]^T + bc[l]) ----------
__global__ void k_mlp(const float* __restrict__ Wc, const float* __restrict__ bc, int l) {
    extern __shared__ float sm[];
    float* Wsh  = sm;              // [132][133] padded (conflict-free stride)
    float* insh = sm + 132 * 133;  // [64][132]
    const float* in  = (l & 1) ? g_hb : g_ha;
    float*       out = (l & 1) ? g_ha : g_hb;

    const int m0 = blockIdx.x * 64;
    const int tid = threadIdx.x;
    const float* W  = Wc + (size_t)l * 129 * 129;
    const float* bb = bc + (size_t)l * 129;

    for (int i = tid; i < 132 * 133; i += 256) {
        int r = i / 133, c = i - r * 133;
        Wsh[i] = (r < 129 && c < 129) ? W[r * 129 + c] : 0.f;
    }
    for (int i = tid; i < 64 * 132; i += 256)
        insh[i] = in[(size_t)m0 * 132 + i];
    __syncthreads();

    const int warp = tid >> 5, lane = tid & 31;
    const int rb = warp * 8;

#pragma unroll
    for (int q = 0; q < 2; q++) {
        float acc[4][5] = {};
        const int r0 = rb + 4 * q;
#pragma unroll 2
        for (int jj = 0; jj < 132; jj++) {
            float h0 = insh[(r0 + 0) * 132 + jj];
            float h1 = insh[(r0 + 1) * 132 + jj];
            float h2 = insh[(r0 + 2) * 132 + jj];
            float h3 = insh[(r0 + 3) * 132 + jj];
#pragma unroll
            for (int cg = 0; cg < 5; cg++) {
                int cc = lane + 32 * cg;
                if (cc < 132) {
                    float w = Wsh[cc * 133 + jj];
                    acc[0][cg] += h0 * w; acc[1][cg] += h1 * w;
                    acc[2][cg] += h2 * w; acc[3][cg] += h3 * w;
                }
            }
        }
#pragma unroll
        for (int cg = 0; cg < 5; cg++) {
            int cc = lane + 32 * cg;
            if (cc < 132) {
                float bv = (cc < 129) ? bb[cc] : 0.f;
#pragma unroll
                for (int i = 0; i < 4; i++)
                    out[(size_t)(m0 + r0 + i) * 132 + cc] = fmaxf(acc[i][cg] + bv, 0.f);
            }
        }
    }
}

// ---------------- K6: head + log_softmax -----------------------------------
__global__ void k_head(const float* __restrict__ Wh, const float* __restrict__ bh,
                       float* __restrict__ out) {
    const int tid = threadIdx.x;
    const int warp = tid >> 5, lane = tid & 31;
    const size_t mrow = (size_t)blockIdx.x * 8 + warp;
    const float* hr = g_ha + mrow * 132;

    float s0 = 0.f, s1 = 0.f;
    for (int j2 = lane; j2 < 129; j2 += 32) {
        float hv = hr[j2];
        s0 += hv * Wh[j2];
        s1 += hv * Wh[129 + j2];
    }
#pragma unroll
    for (int dd = 16; dd; dd >>= 1) {
        s0 += __shfl_xor_sync(0xffffffffu, s0, dd);
        s1 += __shfl_xor_sync(0xffffffffu, s1, dd);
    }
    if (lane == 0) {
        s0 += bh[0]; s1 += bh[1];
        float mx = fmaxf(s0, s1);
        float lse = mx + logf(__expf(s0 - mx) + __expf(s1 - mx));
        out[2 * mrow]     = s0 - lse;
        out[2 * mrow + 1] = s1 - lse;
    }
}

// ---------------- launch ---------------------------------------------------
extern "C" void kernel_launch(void* const* d_in, const int* in_sizes, int n_in,
                              void* d_out, int out_size) {
    const float* x     = (const float*)d_in[0];
    const float* proto = (const float*)d_in[1];
    const float* Wih   = (const float*)d_in[2];
    const float* Whh   = (const float*)d_in[3];
    const float* bih   = (const float*)d_in[4];
    const float* bhh   = (const float*)d_in[5];
    const float* Wc    = (const float*)d_in[6];
    const float* bc    = (const float*)d_in[7];
    const float* Wh    = (const float*)d_in[8];
    const float* bh    = (const float*)d_in[9];
    float* out = (float*)d_out;

    const int smem_xg   = 2 * 64 * 132 * 4;                 // 67584
    const int smem_lstm = (24 * 256 * 4 + 2 * 128) * 4;     // 99328
    const int smem_attn = (2 * 64 * 132 + 64 * 68) * 4;     // 84992
    const int smem_mlp  = (132 * 133 + 64 * 132) * 4;       // 104016

    cudaFuncSetAttribute(k_xg,   cudaFuncAttributeMaxDynamicSharedMemorySize, smem_xg);
    cudaFuncSetAttribute(k_lstm, cudaFuncAttributeMaxDynamicSharedMemorySize, smem_lstm);
    cudaFuncSetAttribute(k_attn, cudaFuncAttributeMaxDynamicSharedMemorySize, smem_attn);
    cudaFuncSetAttribute(k_mlp,  cudaFuncAttributeMaxDynamicSharedMemorySize, smem_mlp);

    k_xg  <<<dim3(512, 8), 256, smem_xg>>>(x, Wih, bih);
    k_lstm<<<16,           256, smem_lstm>>>(Whh, bhh);
    k_attn<<<dim3(32, 16), 256, smem_attn>>>();
    k_feat<<<4096,         256>>>(x, proto);
    for (int l = 0; l < 4; l++)
        k_mlp<<<512, 256, smem_mlp>>>(Wc, bc, l);
    k_head<<<4096, 256>>>(Wh, bh, out);
}